// round 17
// baseline (speedup 1.0000x reference)
#include <cuda_runtime.h>
#include <cuda_fp16.h>
#include <cstdint>

#define BB 2
#define PP 32768
#define VV 5023
#define VV4 5024          // padded to multiple of 4
#define LAT 32
#define HID 128
#define NPTS (BB*PP)
#define NSUB 9
#define ROWB 272          // bytes per activation row (128 fp16 + 16B pad -> conflict-free ldmatrix)

#define NN_CTAS_PER_B 148
#define NN_PTS 222        // ceil(32768/148)

// Weight fragments (fp16, single product), uint4-paired: [s][ks][np][lane]
__device__ uint4 g_wfrag[NSUB * 8 * 8 * 32];
__device__ float g_gshift[NPTS * 3];

// ---------------------------------------------------------------------------
// NN search + gshift + fused weight prep.
// Grid = 2*148 CTAs (2/SM, one wave), 256 threads, 1 point/thread.
// ---------------------------------------------------------------------------
__device__ __forceinline__ float score3(float4 q, float x, float y, float z) {
    return __fmaf_rn(-q.x, x, __fmaf_rn(-q.y, y, __fmaf_rn(-q.z, z, q.w)));
}

__global__ void __launch_bounds__(256, 2)
nn_kernel(const float* __restrict__ pts,
          const float* __restrict__ deformed,
          const float* __restrict__ cano,
          const float* __restrict__ w0, const float* __restrict__ w1,
          const float* __restrict__ w2, const float* __restrict__ w3,
          const float* __restrict__ w4, const float* __restrict__ w5,
          const float* __restrict__ w6, const float* __restrict__ w7) {
    extern __shared__ float4 sv[];

    // ---- fused weight prep (grid covers all 18432 items) ----
    {
        int idx = blockIdx.x * blockDim.x + threadIdx.x;
        if (idx < NSUB * 8 * 8 * 32) {
            int lane = idx & 31;
            int np = (idx >> 5) & 7;
            int ks = (idx >> 8) & 7;
            int s  = idx >> 11;
            const float* w; int Ktot, k0, valid;
            switch (s) {
                case 0: w = w0; Ktot = 110; k0 = 0;   valid = 110; break;
                case 1: w = w1; Ktot = 128; k0 = 0;   valid = 128; break;
                case 2: w = w2; Ktot = 128; k0 = 0;   valid = 128; break;
                case 3: w = w3; Ktot = 128; k0 = 0;   valid = 128; break;
                case 4: w = w4; Ktot = 238; k0 = 0;   valid = 110; break;   // l4 init part
                case 5: w = w4; Ktot = 238; k0 = 110; valid = 128; break;   // l4 hidden part
                case 6: w = w5; Ktot = 128; k0 = 0;   valid = 128; break;
                case 7: w = w6; Ktot = 128; k0 = 0;   valid = 128; break;
                default: w = w7; Ktot = 128; k0 = 0;  valid = 128; break;
            }
            uint32_t frag[2][2];
#pragma unroll
            for (int d = 0; d < 2; ++d) {
                int nt = 2 * np + d;
                int n = nt * 8 + (lane >> 2);
                int kb = ks * 16 + (lane & 3) * 2;
                unsigned short v16[4];
#pragma unroll
                for (int j = 0; j < 4; ++j) {
                    int kk = kb + (j & 1) + (j >> 1) * 8;
                    float v = (kk < valid) ? w[n * Ktot + k0 + kk] : 0.f;
                    v16[j] = __half_as_ushort(__float2half_rn(v));
                }
                frag[d][0] = (uint32_t)v16[0] | ((uint32_t)v16[1] << 16);
                frag[d][1] = (uint32_t)v16[2] | ((uint32_t)v16[3] << 16);
            }
            g_wfrag[idx] = make_uint4(frag[0][0], frag[0][1], frag[1][0], frag[1][1]);
        }
    }

    // ---- stage vertices ----
    const int b = blockIdx.x / NN_CTAS_PER_B;
    const int cta = blockIdx.x % NN_CTAS_PER_B;
    const float* dv = deformed + (size_t)b * VV * 3;
    for (int v = threadIdx.x; v < VV; v += 256) {
        float x = dv[3 * v + 0], y = dv[3 * v + 1], z = dv[3 * v + 2];
        sv[v] = make_float4(x, y, z, 0.5f * (x * x + y * y + z * z));
    }
    if (threadIdx.x == 0) sv[VV] = make_float4(0.f, 0.f, 0.f, 1e30f);  // pad
    __syncthreads();

    const int pl = cta * NN_PTS + threadIdx.x;  // point within batch
    if (threadIdx.x >= NN_PTS || pl >= PP) return;
    const int p = b * PP + pl;

    float ax = pts[p * 3 + 0], ay = pts[p * 3 + 1], az = pts[p * 3 + 2];

    float bs = 1e30f;
    int g = 0;
#pragma unroll 2
    for (int v = 0; v < VV4; v += 4) {
        float4 q0 = sv[v + 0], q1 = sv[v + 1], q2 = sv[v + 2], q3 = sv[v + 3];
        float a0 = score3(q0, ax, ay, az), a1 = score3(q1, ax, ay, az);
        float a2 = score3(q2, ax, ay, az), a3 = score3(q3, ax, ay, az);
        float m = fminf(fminf(a0, a1), fminf(a2, a3));
        g = (m < bs) ? v : g;
        bs = fminf(bs, m);
    }
    // exact index recovery within winning group (bit-identical recompute)
    int iW;
    {
        float4 q0 = sv[g + 0], q1 = sv[g + 1], q2 = sv[g + 2];
        float a0 = score3(q0, ax, ay, az), a1 = score3(q1, ax, ay, az);
        float a2 = score3(q2, ax, ay, az);
        iW = g + ((a0 == bs) ? 0 : (a1 == bs) ? 1 : (a2 == bs) ? 2 : 3);
    }
    {
        float p2 = __fmaf_rn(ax, ax, __fmaf_rn(ay, ay, az * az));
        float w = __expf(-fmaxf(__fmaf_rn(2.f, bs, p2), 0.f));
        float4 q = sv[iW];
        g_gshift[p * 3 + 0] = (cano[iW * 3 + 0] - q.x) * w;
        g_gshift[p * 3 + 1] = (cano[iW * 3 + 1] - q.y) * w;
        g_gshift[p * 3 + 2] = (cano[iW * 3 + 2] - q.z) * w;
    }
}

// ---------------------------------------------------------------------------
// helpers
// ---------------------------------------------------------------------------
__device__ __forceinline__ uint32_t smem_u32(const void* p) {
    uint32_t a;
    asm("{ .reg .u64 t; cvta.to.shared.u64 t, %1; cvt.u32.u64 %0, t; }" : "=r"(a) : "l"(p));
    return a;
}
#define CP_ASYNC16(dst, src) \
    asm volatile("cp.async.cg.shared.global [%0], [%1], 16;" :: "r"(dst), "l"(src))
#define CP_COMMIT() asm volatile("cp.async.commit_group;" ::: "memory")
#define CP_WAIT1()  asm volatile("cp.async.wait_group 1;" ::: "memory")
#define CP_WAIT0()  asm volatile("cp.async.wait_group 0;" ::: "memory")

__device__ __forceinline__ void ldmA(uint32_t a[4], uint32_t su, int rowbase, int kbase, int lane) {
    int grp = lane >> 3, ri = lane & 7;
    int row = rowbase + ri + ((grp & 1) << 3);
    int col = kbase + ((grp & 2) << 2);
    uint32_t addr = su + (uint32_t)(row * ROWB + col * 2);
    asm volatile("ldmatrix.sync.aligned.m8n8.x4.shared.b16 {%0,%1,%2,%3}, [%4];"
                 : "=r"(a[0]), "=r"(a[1]), "=r"(a[2]), "=r"(a[3]) : "r"(addr));
}
__device__ __forceinline__ void mma16816(float c[4], const uint32_t a[4], uint32_t b0, uint32_t b1) {
    asm volatile(
        "mma.sync.aligned.m16n8k16.row.col.f32.f16.f16.f32 "
        "{%0,%1,%2,%3},{%4,%5,%6,%7},{%8,%9},{%0,%1,%2,%3};"
        : "+f"(c[0]), "+f"(c[1]), "+f"(c[2]), "+f"(c[3])
        : "r"(a[0]), "r"(a[1]), "r"(a[2]), "r"(a[3]), "r"(b0), "r"(b1));
}
__device__ __forceinline__ uint32_t pack_h2(float lo, float hi) {
    __half2 h = __floats2half2_rn(lo, hi);
    return *reinterpret_cast<uint32_t*>(&h);
}

// ---------------------------------------------------------------------------
// feature build (one point per thread, tid < 128) -> single fp16 buffer
// ---------------------------------------------------------------------------
__device__ void build_feat(char* act, int row, int bp,
                           const float* __restrict__ pts, const float* __restrict__ latent) {
    __half* a = (__half*)(act + row * ROWB);
    float px = pts[bp * 3 + 0], py = pts[bp * 3 + 1], pz = pts[bp * 3 + 2];
    float gx = g_gshift[bp * 3 + 0], gy = g_gshift[bp * 3 + 1], gz = g_gshift[bp * 3 + 2];
    a[0] = __float2half_rn(px); a[1] = __float2half_rn(py); a[2] = __float2half_rn(pz);
#pragma unroll
    for (int l = 0; l < 10; ++l) {
        float f = (float)(1 << l);
        float s, c;
        __sincosf(px * f, &s, &c); a[3 + 6 * l + 0] = __float2half_rn(s); a[3 + 6 * l + 3] = __float2half_rn(c);
        __sincosf(py * f, &s, &c); a[3 + 6 * l + 1] = __float2half_rn(s); a[3 + 6 * l + 4] = __float2half_rn(c);
        __sincosf(pz * f, &s, &c); a[3 + 6 * l + 2] = __float2half_rn(s); a[3 + 6 * l + 5] = __float2half_rn(c);
    }
    a[63] = __float2half_rn(gx); a[64] = __float2half_rn(gy); a[65] = __float2half_rn(gz);
#pragma unroll
    for (int l = 0; l < 2; ++l) {
        float f = (float)(1 << l);
        float s, c;
        __sincosf(gx * f, &s, &c); a[66 + 6 * l + 0] = __float2half_rn(s); a[66 + 6 * l + 3] = __float2half_rn(c);
        __sincosf(gy * f, &s, &c); a[66 + 6 * l + 1] = __float2half_rn(s); a[66 + 6 * l + 4] = __float2half_rn(c);
        __sincosf(gz * f, &s, &c); a[66 + 6 * l + 2] = __float2half_rn(s); a[66 + 6 * l + 5] = __float2half_rn(c);
    }
#pragma unroll
    for (int j = 0; j < 32; ++j) a[78 + j] = __float2half_rn(latent[(size_t)bp * LAT + j]);
    __half z = __float2half_rn(0.f);
#pragma unroll
    for (int j = 110; j < 128; ++j) a[j] = z;
}

// ---------------------------------------------------------------------------
// SMEM layout (256-thread CTA, 128 points, 8 warps x 16 rows) -> 2 CTAs/SM
// Double-buffered 32KB weight stages.
// ---------------------------------------------------------------------------
#define OFF_A    0
#define OFF_W0   34816
#define OFF_W1   67584
#define OFF_BIAS 100352
#define OFF_WOUT 104448
#define OFF_BOUT 105984
#define SMEM_MLP 106000

__global__ void __launch_bounds__(256, 2)
mlp_mma_kernel(const float* __restrict__ pts, const float* __restrict__ latent,
               const float* __restrict__ b0, const float* __restrict__ b1,
               const float* __restrict__ b2, const float* __restrict__ b3,
               const float* __restrict__ b4, const float* __restrict__ b5,
               const float* __restrict__ b6, const float* __restrict__ b7,
               const float* __restrict__ w_out, const float* __restrict__ b_out,
               float* __restrict__ out) {
    extern __shared__ char sm[];
    char* act = sm + OFF_A;
    float* sbias = (float*)(sm + OFF_BIAS);
    float* swout = (float*)(sm + OFF_WOUT);
    float* sbout = (float*)(sm + OFF_BOUT);

    const int tid = threadIdx.x;
    const int wid = tid >> 5;
    const int lane = tid & 31;
    const int bp0 = blockIdx.x * 128;
    const int bp = bp0 + tid;          // valid for tid < 128
    const uint32_t suA = smem_u32(act);
    const uint32_t suW[2] = {smem_u32(sm + OFF_W0), smem_u32(sm + OFF_W1)};
    const int mrow = wid * 16;         // 8 warps x 16 rows

    // step tables
    const int stepS[NSUB]    = {0, 1, 2, 3, 5, 4, 6, 7, 8};
    const int stepZero[NSUB] = {1, 1, 1, 1, 1, 0, 1, 1, 1};
    const int stepEpi[NSUB]  = {0, 1, 2, 3, -1, 4, 5, 6, 7};
    const int stepReb[NSUB]  = {0, 0, 0, 0, 0, 1, 0, 0, 0};

    // prologue: prefetch L0 into buf0 (32KB = 2048 uint4, 8 per thread)
    {
        const char* src = (const char*)(g_wfrag + (size_t)stepS[0] * 2048);
#pragma unroll
        for (int i = 0; i < 8; ++i) {
            uint32_t off = (uint32_t)(tid + 256 * i) * 16u;
            CP_ASYNC16(suW[0] + off, src + off);
        }
        CP_COMMIT();
    }

    // stage biases / head weights
    {
        const float* bs[8] = {b0, b1, b2, b3, b4, b5, b6, b7};
        for (int i = tid; i < 1024; i += 256) sbias[i] = bs[i >> 7][i & 127];
        for (int i = tid; i < 384; i += 256) swout[i] = w_out[i];
        if (tid < 3) sbout[tid] = b_out[tid];
    }

    if (tid < 128) build_feat(act, tid, bp, pts, latent);

    float c[16][4];

#pragma unroll 1
    for (int st = 0; st < NSUB; ++st) {
        // prefetch next layer into the other buffer, then wait for this layer
        if (st + 1 < NSUB) {
            const char* src = (const char*)(g_wfrag + (size_t)stepS[st + 1] * 2048);
            uint32_t dst = suW[(st + 1) & 1];
#pragma unroll
            for (int i = 0; i < 8; ++i) {
                uint32_t off = (uint32_t)(tid + 256 * i) * 16u;
                CP_ASYNC16(dst + off, src + off);
            }
            CP_COMMIT();
            CP_WAIT1();
        } else {
            CP_WAIT0();
        }
        __syncthreads();

        if (stepZero[st]) {
#pragma unroll
            for (int nt = 0; nt < 16; ++nt)
#pragma unroll
                for (int j = 0; j < 4; ++j) c[nt][j] = 0.f;
        }
        if (stepReb[st]) {
            if (tid < 128) build_feat(act, tid, bp, pts, latent);
            __syncthreads();   // feature rows cross warp ownership
        }

        // ---- software-pipelined MMA: B-register rotation + A prefetch ----
        {
            const char* wbuf = sm + (((st & 1) == 0) ? OFF_W0 : OFF_W1);
            uint32_t a0[4];
            ldmA(a0, suA, mrow, 0, lane);
            uint4 B = *reinterpret_cast<const uint4*>(wbuf + (uint32_t)(0 * 32 + lane) * 16u);
#pragma unroll
            for (int i = 0; i < 64; ++i) {
                const int np = i & 7;
                const int ks = i >> 3;
                uint4 Bn;
                if (i < 63)
                    Bn = *reinterpret_cast<const uint4*>(wbuf + (uint32_t)((i + 1) * 32 + lane) * 16u);
                uint32_t a0n[4];
                if (np == 7 && ks < 7)
                    ldmA(a0n, suA, mrow, (ks + 1) * 16, lane);
                mma16816(c[2 * np], a0, B.x, B.y);
                mma16816(c[2 * np + 1], a0, B.z, B.w);
                if (i < 63) B = Bn;
                if (np == 7 && ks < 7) {
#pragma unroll
                    for (int j = 0; j < 4; ++j) a0[j] = a0n[j];
                }
            }
        }

        const int l = stepEpi[st];
        if (l >= 0) {
            __syncwarp();
            if (l < 7) {
                const float* bia = sbias + l * 128;
                const int r0 = mrow + (lane >> 2);
#pragma unroll
                for (int nt = 0; nt < 16; ++nt) {
                    const int n0 = nt * 8 + (lane & 3) * 2;
                    float2 bb = *reinterpret_cast<const float2*>(bia + n0);
                    float v0 = fmaxf(c[nt][0] + bb.x, 0.f);
                    float v1 = fmaxf(c[nt][1] + bb.y, 0.f);
                    float v2 = fmaxf(c[nt][2] + bb.x, 0.f);
                    float v3 = fmaxf(c[nt][3] + bb.y, 0.f);
                    *(uint32_t*)(act + r0 * ROWB + n0 * 2) = pack_h2(v0, v1);
                    *(uint32_t*)(act + (r0 + 8) * ROWB + n0 * 2) = pack_h2(v2, v3);
                }
                __syncwarp();
            } else {
                // final layer: write pre-activation last_feat, compute output head
                const float* bia = sbias + 7 * 128;
                float* out2 = out + (size_t)NPTS * 3;
                const int r0 = mrow + (lane >> 2);
                float hs[2][3];
#pragma unroll
                for (int rr = 0; rr < 2; ++rr)
#pragma unroll
                    for (int cc = 0; cc < 3; ++cc) hs[rr][cc] = 0.f;
#pragma unroll
                for (int nt = 0; nt < 16; ++nt) {
                    const int n0 = nt * 8 + (lane & 3) * 2;
                    float2 bb = *reinterpret_cast<const float2*>(bia + n0);
                    float pre0 = c[nt][0] + bb.x;
                    float pre1 = c[nt][1] + bb.y;
                    float pre2 = c[nt][2] + bb.x;
                    float pre3 = c[nt][3] + bb.y;
                    *(float2*)(out2 + (size_t)(bp0 + r0) * HID + n0) = make_float2(pre0, pre1);
                    *(float2*)(out2 + (size_t)(bp0 + r0 + 8) * HID + n0) = make_float2(pre2, pre3);
                    float a0 = fmaxf(pre0, 0.f), a1 = fmaxf(pre1, 0.f);
                    float a2 = fmaxf(pre2, 0.f), a3 = fmaxf(pre3, 0.f);
#pragma unroll
                    for (int cc = 0; cc < 3; ++cc) {
                        hs[0][cc] = fmaf(a0, swout[cc * 128 + n0], hs[0][cc]);
                        hs[0][cc] = fmaf(a1, swout[cc * 128 + n0 + 1], hs[0][cc]);
                        hs[1][cc] = fmaf(a2, swout[cc * 128 + n0], hs[1][cc]);
                        hs[1][cc] = fmaf(a3, swout[cc * 128 + n0 + 1], hs[1][cc]);
                    }
                }
#pragma unroll
                for (int rr = 0; rr < 2; ++rr)
#pragma unroll
                    for (int cc = 0; cc < 3; ++cc) {
                        float v = hs[rr][cc];
                        v += __shfl_xor_sync(0xffffffffu, v, 1);
                        v += __shfl_xor_sync(0xffffffffu, v, 2);
                        hs[rr][cc] = v;
                    }
                if ((lane & 3) == 0) {
#pragma unroll
                    for (int rr = 0; rr < 2; ++rr) {
                        const int r = mrow + (lane >> 2) + rr * 8;
                        const int gp = bp0 + r;
#pragma unroll
                        for (int cc = 0; cc < 3; ++cc)
                            out[gp * 3 + cc] = pts[gp * 3 + cc] + g_gshift[gp * 3 + cc]
                                               + hs[rr][cc] + sbout[cc];
                    }
                }
            }
        }
        __syncthreads();  // protect buf[st&1] before it is refilled at iter st+1
    }
}

// ---------------------------------------------------------------------------
extern "C" void kernel_launch(void* const* d_in, const int* in_sizes, int n_in,
                              void* d_out, int out_size) {
    const float* pts      = (const float*)d_in[0];
    const float* deformed = (const float*)d_in[1];
    const float* cano     = (const float*)d_in[2];
    const float* latent   = (const float*)d_in[3];
    const float* w[8];
    const float* b[8];
    for (int i = 0; i < 8; ++i) {
        w[i] = (const float*)d_in[4 + 2 * i];
        b[i] = (const float*)d_in[5 + 2 * i];
    }
    const float* w_out = (const float*)d_in[20];
    const float* b_out = (const float*)d_in[21];
    float* out = (float*)d_out;

    const int smem_nn = VV4 * 16;  // 80384
    cudaFuncSetAttribute(nn_kernel, cudaFuncAttributeMaxDynamicSharedMemorySize, smem_nn);
    cudaFuncSetAttribute(mlp_mma_kernel, cudaFuncAttributeMaxDynamicSharedMemorySize, SMEM_MLP);

    nn_kernel<<<BB * NN_CTAS_PER_B, 256, smem_nn>>>(pts, deformed, cano,
                                                    w[0], w[1], w[2], w[3], w[4], w[5], w[6], w[7]);
    mlp_mma_kernel<<<NPTS / 128, 256, SMEM_MLP>>>(pts, latent, b[0], b[1], b[2], b[3], b[4],
                                                  b[5], b[6], b[7], w_out, b_out, out);
}